// round 1
// baseline (speedup 1.0000x reference)
#include <cuda_runtime.h>
#include <math.h>

#define NND 50000
#define NE  800000
#define NP  262144
#define FIN 572
#define C1  256     // H1
#define C2  128     // H2
#define NC  65

// ---------------- scratch (static device globals; no allocs) ----------------
__device__ float g_h[(size_t)NND * 512];      // post-W features [N, 2*256]
__device__ float g_feat[(size_t)NND * C1];    // node features   [N, 256]
__device__ float g_s[NND * 2];
__device__ float g_d[NND * 2];
__device__ float g_z1[(size_t)NP * C2];
__device__ float g_z2[(size_t)NP * C2];
__device__ float g_sums[512];                 // per-channel sum / sumsq
__device__ int   g_deg[NND];
__device__ int   g_rowptr[NND + 1];
__device__ int   g_cursor[NND];
__device__ int   g_csr[NE];

// ---------------- small utils ----------------
__device__ __forceinline__ float lrelu(float x) { return x > 0.f ? x : 0.2f * x; }

__global__ void zero_i(int* p, int n) {
    int i = blockIdx.x * blockDim.x + threadIdx.x;
    if (i < n) p[i] = 0;
}
__global__ void zero_f(float* p, int n) {
    int i = blockIdx.x * blockDim.x + threadIdx.x;
    if (i < n) p[i] = 0.f;
}

// ---------------- CSR build ----------------
__global__ void count_deg(const int* __restrict__ ei, int* __restrict__ deg) {
    int e = blockIdx.x * blockDim.x + threadIdx.x;
    if (e < NE) atomicAdd(&deg[ei[NE + e]], 1);
}

__global__ void scan_kernel(const int* __restrict__ deg, int* __restrict__ rowptr,
                            int* __restrict__ cursor) {
    __shared__ int sh[1024];
    __shared__ int carry_s;
    int t = threadIdx.x;
    if (t == 0) { carry_s = 0; rowptr[0] = 0; }
    __syncthreads();
    for (int base = 0; base < NND; base += 1024) {
        int v = (base + t < NND) ? deg[base + t] : 0;
        sh[t] = v;
        __syncthreads();
        for (int off = 1; off < 1024; off <<= 1) {
            int add = (t >= off) ? sh[t - off] : 0;
            __syncthreads();
            sh[t] += add;
            __syncthreads();
        }
        int incl = sh[t];
        int carry = carry_s;
        if (base + t < NND) {
            rowptr[base + t + 1] = carry + incl;
            cursor[base + t]     = carry + incl - v;
        }
        __syncthreads();
        if (t == 1023) carry_s = carry + incl;
        __syncthreads();
    }
}

__global__ void fill_csr(const int* __restrict__ ei, int* __restrict__ cursor,
                         int* __restrict__ csr) {
    int e = blockIdx.x * blockDim.x + threadIdx.x;
    if (e < NE) {
        int dn = ei[NE + e];
        int pos = atomicAdd(&cursor[dn], 1);
        csr[pos] = ei[e];
    }
}

// ---------------- generic fp32 tiled GEMM: C = A @ B (+bias) ----------------
// GATHER variant: A row p = concat(F[id0[p]], F[id1[p]]), each baseW wide.
template <bool GATHER>
__global__ void gemm_tiled(const float* __restrict__ A, const float* __restrict__ B,
                           const float* __restrict__ bias, float* __restrict__ C,
                           int M, int N, int K,
                           const int* __restrict__ id0, const int* __restrict__ id1,
                           int baseW) {
    __shared__ float As[16][64];
    __shared__ float Bs[16][64];
    int tid = threadIdx.x;
    int tx = tid & 15, ty = tid >> 4;
    int rowBase = blockIdx.y * 64;
    int colBase = blockIdx.x * 64;
    float acc[4][4] = {};
    for (int k0 = 0; k0 < K; k0 += 16) {
#pragma unroll
        for (int i = 0; i < 4; i++) {
            int idx = tid + 256 * i;
            int r = idx >> 4, kk = idx & 15;
            int row = rowBase + r;
            int k = k0 + kk;
            float v = 0.f;
            if (row < M && k < K) {
                if (GATHER) {
                    int nid = (k < baseW) ? id0[row] : id1[row];
                    int kc  = (k < baseW) ? k : k - baseW;
                    v = A[(size_t)nid * baseW + kc];
                } else {
                    v = A[(size_t)row * K + k];
                }
            }
            As[kk][r] = v;
        }
#pragma unroll
        for (int i = 0; i < 4; i++) {
            int idx = tid + 256 * i;
            int kk = idx >> 6, c = idx & 63;
            int k = k0 + kk;
            int col = colBase + c;
            Bs[kk][c] = (k < K && col < N) ? B[(size_t)k * N + col] : 0.f;
        }
        __syncthreads();
#pragma unroll
        for (int kk = 0; kk < 16; kk++) {
            float a[4], b[4];
#pragma unroll
            for (int i = 0; i < 4; i++) a[i] = As[kk][ty * 4 + i];
#pragma unroll
            for (int j = 0; j < 4; j++) b[j] = Bs[kk][tx * 4 + j];
#pragma unroll
            for (int i = 0; i < 4; i++)
#pragma unroll
                for (int j = 0; j < 4; j++) acc[i][j] = fmaf(a[i], b[j], acc[i][j]);
        }
        __syncthreads();
    }
#pragma unroll
    for (int i = 0; i < 4; i++) {
        int row = rowBase + ty * 4 + i;
        if (row >= M) continue;
#pragma unroll
        for (int j = 0; j < 4; j++) {
            int col = colBase + tx * 4 + j;
            if (col < N) {
                float v = acc[i][j];
                if (bias) v += bias[col];
                C[(size_t)row * N + col] = v;
            }
        }
    }
}

// ---------------- attention logits s,d per (node, head) ----------------
__global__ void sdot_kernel(const float* __restrict__ h, const float* __restrict__ a_src,
                            const float* __restrict__ a_dst, float* __restrict__ s,
                            float* __restrict__ d) {
    __shared__ float4 sh[256];
    int n = blockIdx.x, t = threadIdx.x;
    float h0 = h[(size_t)n * 512 + t];
    float h1 = h[(size_t)n * 512 + 256 + t];
    float4 v = make_float4(h0 * a_src[t], h0 * a_dst[t],
                           h1 * a_src[256 + t], h1 * a_dst[256 + t]);
    sh[t] = v;
    __syncthreads();
    for (int o = 128; o > 0; o >>= 1) {
        if (t < o) {
            float4 w = sh[t + o];
            float4 m = sh[t];
            m.x += w.x; m.y += w.y; m.z += w.z; m.w += w.w;
            sh[t] = m;
        }
        __syncthreads();
    }
    if (t == 0) {
        float4 r = sh[0];
        s[2 * n] = r.x; d[2 * n] = r.y; s[2 * n + 1] = r.z; d[2 * n + 1] = r.w;
    }
}

__device__ __forceinline__ float4 f4fma(float4 a, float w, float4 acc) {
    acc.x = fmaf(a.x, w, acc.x); acc.y = fmaf(a.y, w, acc.y);
    acc.z = fmaf(a.z, w, acc.z); acc.w = fmaf(a.w, w, acc.w);
    return acc;
}

// ---------------- gather-based GAT softmax + aggregation (warp/node) --------
__global__ void gat_aggregate(const float* __restrict__ h, const float* __restrict__ s,
                              const float* __restrict__ d, const int* __restrict__ rowptr,
                              const int* __restrict__ csr, const float* __restrict__ bias,
                              float* __restrict__ out) {
    int warp = (blockIdx.x * blockDim.x + threadIdx.x) >> 5;
    int lane = threadIdx.x & 31;
    if (warp >= NND) return;
    int n = warp;
    int beg = rowptr[n], end = rowptr[n + 1];
    float d0 = d[2 * n], d1 = d[2 * n + 1];
    float self0 = lrelu(s[2 * n] + d0);
    float self1 = lrelu(s[2 * n + 1] + d1);

    // pass 1: max
    float m0 = self0, m1 = self1;
    for (int i = beg + lane; i < end; i += 32) {
        int src = csr[i];
        m0 = fmaxf(m0, lrelu(s[2 * src] + d0));
        m1 = fmaxf(m1, lrelu(s[2 * src + 1] + d1));
    }
#pragma unroll
    for (int o = 16; o; o >>= 1) {
        m0 = fmaxf(m0, __shfl_xor_sync(0xffffffffu, m0, o));
        m1 = fmaxf(m1, __shfl_xor_sync(0xffffffffu, m1, o));
    }
    // pass 2: sum of exp
    float z0 = (lane == 0) ? __expf(self0 - m0) : 0.f;
    float z1 = (lane == 0) ? __expf(self1 - m1) : 0.f;
    for (int i = beg + lane; i < end; i += 32) {
        int src = csr[i];
        z0 += __expf(lrelu(s[2 * src] + d0) - m0);
        z1 += __expf(lrelu(s[2 * src + 1] + d1) - m1);
    }
#pragma unroll
    for (int o = 16; o; o >>= 1) {
        z0 += __shfl_xor_sync(0xffffffffu, z0, o);
        z1 += __shfl_xor_sync(0xffffffffu, z1, o);
    }
    float inv0 = 1.f / (z0 + 1e-16f), inv1 = 1.f / (z1 + 1e-16f);

    // pass 3: weighted accumulate over 512 channels (lane holds 4x float4)
    const float4* h4 = (const float4*)h;
    float4 a0 = {0, 0, 0, 0}, a1 = a0, a2 = a0, a3 = a0;
    {
        float w0 = __expf(self0 - m0) * inv0;
        float w1 = __expf(self1 - m1) * inv1;
        const float4* row = h4 + (size_t)n * 128;
        a0 = f4fma(row[lane], w0, a0);
        a1 = f4fma(row[lane + 32], w0, a1);
        a2 = f4fma(row[lane + 64], w1, a2);
        a3 = f4fma(row[lane + 96], w1, a3);
    }
    for (int i = beg; i < end; i++) {
        int src = csr[i];  // uniform across warp -> broadcast load
        float w0 = __expf(lrelu(s[2 * src] + d0) - m0) * inv0;
        float w1 = __expf(lrelu(s[2 * src + 1] + d1) - m1) * inv1;
        const float4* row = h4 + (size_t)src * 128;
        a0 = f4fma(row[lane], w0, a0);
        a1 = f4fma(row[lane + 32], w0, a1);
        a2 = f4fma(row[lane + 64], w1, a2);
        a3 = f4fma(row[lane + 96], w1, a3);
    }
    // mean over heads + bias; write [N, 256]
    const float4* b4 = (const float4*)bias;
    float4 bA = b4[lane], bB = b4[lane + 32];
    float4 r0, r1;
    r0.x = (a0.x + a2.x) * 0.5f + bA.x; r0.y = (a0.y + a2.y) * 0.5f + bA.y;
    r0.z = (a0.z + a2.z) * 0.5f + bA.z; r0.w = (a0.w + a2.w) * 0.5f + bA.w;
    r1.x = (a1.x + a3.x) * 0.5f + bB.x; r1.y = (a1.y + a3.y) * 0.5f + bB.y;
    r1.z = (a1.z + a3.z) * 0.5f + bB.z; r1.w = (a1.w + a3.w) * 0.5f + bB.w;
    float4* o4 = (float4*)out;
    o4[(size_t)n * 64 + lane] = r0;
    o4[(size_t)n * 64 + lane + 32] = r1;
}

// ---------------- batch norm (two pass) ----------------
__global__ void bn_stats(const float* __restrict__ x, float* __restrict__ sums,
                         int rows, int C, int rowsPerBlock) {
    int c = threadIdx.x;  // blockDim.x == C
    int r0 = blockIdx.x * rowsPerBlock;
    int r1 = min(rows, r0 + rowsPerBlock);
    float s = 0.f, q = 0.f;
    for (int r = r0; r < r1; r++) {
        float v = x[(size_t)r * C + c];
        s += v;
        q += v * v;
    }
    atomicAdd(&sums[c], s);
    atomicAdd(&sums[C + c], q);
}

__global__ void bn_apply(float* __restrict__ x, const float* __restrict__ sums,
                         const float* __restrict__ g, const float* __restrict__ b,
                         int rows, int C) {
    size_t i = (size_t)blockIdx.x * blockDim.x + threadIdx.x;
    if (i >= (size_t)rows * C) return;
    int c = (int)(i % C);
    float mu = sums[c] / rows;
    float var = sums[C + c] / rows - mu * mu;
    float y = g[c] * (x[i] - mu) * rsqrtf(var + 1e-5f) + b[c];
    x[i] = fmaxf(y, 0.f);
}

// ---------------- launch ----------------
extern "C" void kernel_launch(void* const* d_in, const int* in_sizes, int n_in,
                              void* d_out, int out_size) {
    const int*   edge_index = (const int*)d_in[0];
    const float* x      = (const float*)d_in[1];
    const int*   edge_id = (const int*)d_in[2];
    const float* W1     = (const float*)d_in[3];
    const float* a_src1 = (const float*)d_in[4];
    const float* a_dst1 = (const float*)d_in[5];
    const float* b1     = (const float*)d_in[6];
    const float* bn1_g  = (const float*)d_in[7];
    const float* bn1_b  = (const float*)d_in[8];
    const float* W2     = (const float*)d_in[9];
    const float* a_src2 = (const float*)d_in[10];
    const float* a_dst2 = (const float*)d_in[11];
    const float* b2     = (const float*)d_in[12];
    const float* bn2_g  = (const float*)d_in[13];
    const float* bn2_b  = (const float*)d_in[14];
    const float* lw1    = (const float*)d_in[15];
    const float* lb1    = (const float*)d_in[16];
    const float* bn3_g  = (const float*)d_in[17];
    const float* bn3_b  = (const float*)d_in[18];
    const float* lw2    = (const float*)d_in[19];
    const float* lb2    = (const float*)d_in[20];
    const float* bn4_g  = (const float*)d_in[21];
    const float* bn4_b  = (const float*)d_in[22];
    const float* fw     = (const float*)d_in[23];
    const float* fb     = (const float*)d_in[24];
    float* out = (float*)d_out;

    float *h, *feat, *s, *d, *z1, *z2, *sums;
    int *deg, *rowptr, *cursor, *csr;
    cudaGetSymbolAddress((void**)&h, g_h);
    cudaGetSymbolAddress((void**)&feat, g_feat);
    cudaGetSymbolAddress((void**)&s, g_s);
    cudaGetSymbolAddress((void**)&d, g_d);
    cudaGetSymbolAddress((void**)&z1, g_z1);
    cudaGetSymbolAddress((void**)&z2, g_z2);
    cudaGetSymbolAddress((void**)&sums, g_sums);
    cudaGetSymbolAddress((void**)&deg, g_deg);
    cudaGetSymbolAddress((void**)&rowptr, g_rowptr);
    cudaGetSymbolAddress((void**)&cursor, g_cursor);
    cudaGetSymbolAddress((void**)&csr, g_csr);

    // ---- CSR build (destination-sorted adjacency) ----
    zero_i<<<(NND + 255) / 256, 256>>>(deg, NND);
    count_deg<<<(NE + 255) / 256, 256>>>(edge_index, deg);
    scan_kernel<<<1, 1024>>>(deg, rowptr, cursor);
    fill_csr<<<(NE + 255) / 256, 256>>>(edge_index, cursor, csr);

    dim3 gemmBlk(256);
    // ---- GAT layer 1 ----
    gemm_tiled<false><<<dim3(8, (NND + 63) / 64), gemmBlk>>>(
        x, W1, nullptr, h, NND, 512, FIN, nullptr, nullptr, 0);
    sdot_kernel<<<NND, 256>>>(h, a_src1, a_dst1, s, d);
    gat_aggregate<<<(NND * 32 + 255) / 256, 256>>>(h, s, d, rowptr, csr, b1, feat);
    zero_f<<<2, 256>>>(sums, 512);
    bn_stats<<<(NND + 511) / 512, 256>>>(feat, sums, NND, C1, 512);
    bn_apply<<<(int)(((size_t)NND * C1 + 255) / 256), 256>>>(feat, sums, bn1_g, bn1_b, NND, C1);

    // ---- GAT layer 2 ----
    gemm_tiled<false><<<dim3(8, (NND + 63) / 64), gemmBlk>>>(
        feat, W2, nullptr, h, NND, 512, C1, nullptr, nullptr, 0);
    sdot_kernel<<<NND, 256>>>(h, a_src2, a_dst2, s, d);
    gat_aggregate<<<(NND * 32 + 255) / 256, 256>>>(h, s, d, rowptr, csr, b2, feat);
    zero_f<<<2, 256>>>(sums, 512);
    bn_stats<<<(NND + 511) / 512, 256>>>(feat, sums, NND, C1, 512);
    bn_apply<<<(int)(((size_t)NND * C1 + 255) / 256), 256>>>(feat, sums, bn2_g, bn2_b, NND, C1);

    // ---- pair MLP ----
    gemm_tiled<true><<<dim3(2, NP / 64), gemmBlk>>>(
        feat, lw1, lb1, z1, NP, C2, 512, edge_id, edge_id + NP, C1);
    zero_f<<<1, 256>>>(sums, 256);
    bn_stats<<<(NP + 1023) / 1024, C2>>>(z1, sums, NP, C2, 1024);
    bn_apply<<<(int)(((size_t)NP * C2 + 255) / 256), 256>>>(z1, sums, bn3_g, bn3_b, NP, C2);

    gemm_tiled<false><<<dim3(2, NP / 64), gemmBlk>>>(
        z1, lw2, lb2, z2, NP, C2, C2, nullptr, nullptr, 0);
    zero_f<<<1, 256>>>(sums, 256);
    bn_stats<<<(NP + 1023) / 1024, C2>>>(z2, sums, NP, C2, 1024);
    bn_apply<<<(int)(((size_t)NP * C2 + 255) / 256), 256>>>(z2, sums, bn4_g, bn4_b, NP, C2);

    gemm_tiled<false><<<dim3(2, NP / 64), gemmBlk>>>(
        z2, fw, fb, out, NP, NC, C2, nullptr, nullptr, 0);
}

// round 5
// speedup vs baseline: 2.4498x; 2.4498x over previous
#include <cuda_runtime.h>
#include <cuda_bf16.h>
#include <mma.h>
#include <cstdint>
#include <math.h>

using namespace nvcuda;

#define NND 50000
#define NE  800000
#define NP  262144
#define FIN 572
#define C1  256     // H1
#define C2  128     // H2
#define NC  65

// ======================= scratch =======================
__device__ float g_h[(size_t)NND * 512];
__device__ float g_feat[(size_t)NND * C1];
__device__ float g_s[NND * 2];
__device__ float g_d[NND * 2];
__device__ float g_z1[(size_t)NP * C2];
__device__ float g_z2[(size_t)NP * C2];
__device__ float g_sums[512];
__device__ int   g_deg[NND];
__device__ int   g_rowptr[NND + 1];
__device__ int   g_cursor[NND];
__device__ int   g_csr[NE];
// transposed, zero-padded weights [N_pad, kpad] (fp32)
__device__ float g_w1t[512 * 576];
__device__ float g_w2t[512 * 256];
__device__ float g_lw1t[128 * 512];
__device__ float g_lw2t[128 * 128];
__device__ float g_fwt[128 * 128];

__device__ __forceinline__ float lrelu(float x) { return x > 0.f ? x : 0.2f * x; }

__global__ void zero_i(int* p, int n) {
    int i = blockIdx.x * blockDim.x + threadIdx.x;
    if (i < n) p[i] = 0;
}
__global__ void zero_f(float* p, int n) {
    int i = blockIdx.x * blockDim.x + threadIdx.x;
    if (i < n) p[i] = 0.f;
}

// Wt[n*kpad + k] = (k<K && n<N) ? W[k*N+n] : 0
__global__ void transposeW(const float* __restrict__ W, float* __restrict__ Wt,
                           int K, int N, int rows, int kpad) {
    int i = blockIdx.x * blockDim.x + threadIdx.x;
    int tot = rows * kpad;
    if (i >= tot) return;
    int n = i / kpad, k = i - n * kpad;
    Wt[i] = (k < K && n < N) ? W[(size_t)k * N + n] : 0.f;
}

// ======================= CSR build =======================
__global__ void count_deg(const int* __restrict__ ei, int* __restrict__ deg) {
    int e = blockIdx.x * blockDim.x + threadIdx.x;
    if (e < NE) atomicAdd(&deg[ei[NE + e]], 1);
}

__global__ void scan_kernel(const int* __restrict__ deg, int* __restrict__ rowptr,
                            int* __restrict__ cursor) {
    __shared__ int sh[1024];
    __shared__ int carry_s;
    int t = threadIdx.x;
    if (t == 0) { carry_s = 0; rowptr[0] = 0; }
    __syncthreads();
    for (int base = 0; base < NND; base += 1024) {
        int v = (base + t < NND) ? deg[base + t] : 0;
        sh[t] = v;
        __syncthreads();
        for (int off = 1; off < 1024; off <<= 1) {
            int add = (t >= off) ? sh[t - off] : 0;
            __syncthreads();
            sh[t] += add;
            __syncthreads();
        }
        int incl = sh[t];
        int carry = carry_s;
        if (base + t < NND) {
            rowptr[base + t + 1] = carry + incl;
            cursor[base + t]     = carry + incl - v;
        }
        __syncthreads();
        if (t == 1023) carry_s = carry + incl;
        __syncthreads();
    }
}

__global__ void fill_csr(const int* __restrict__ ei, int* __restrict__ cursor,
                         int* __restrict__ csr) {
    int e = blockIdx.x * blockDim.x + threadIdx.x;
    if (e < NE) {
        int dn = ei[NE + e];
        int pos = atomicAdd(&cursor[dn], 1);
        csr[pos] = ei[e];
    }
}

// ======================= bf16x3 wmma GEMM =======================
// C[M,Nc] = A[M,K] @ Bt^T  (Bt is [N_pad, kpad], fp32, zero padded).
// CTA tile 128x128, 8 warps (2x4), warp tile 64x32, BK=32.
// bf16 split compensation: C += Ah*Bh + Al*Bh + Ah*Bl.
#define TROW 40                 // padded row length (elements) for SMEM tiles
#define TILE_B (128 * TROW * 2) // bytes per bf16 tile buffer (10240)
#define MG_SMEM 65536           // union: 4 tiles (40KB) | epilogue 128x128 f32 (64KB)

__device__ __forceinline__ void split_store(float4 v, __nv_bfloat16* hi,
                                            __nv_bfloat16* lo) {
    __nv_bfloat16 h0 = __float2bfloat16(v.x);
    __nv_bfloat16 h1 = __float2bfloat16(v.y);
    __nv_bfloat16 h2 = __float2bfloat16(v.z);
    __nv_bfloat16 h3 = __float2bfloat16(v.w);
    __nv_bfloat16 l0 = __float2bfloat16(v.x - __bfloat162float(h0));
    __nv_bfloat16 l1 = __float2bfloat16(v.y - __bfloat162float(h1));
    __nv_bfloat16 l2 = __float2bfloat16(v.z - __bfloat162float(h2));
    __nv_bfloat16 l3 = __float2bfloat16(v.w - __bfloat162float(h3));
    __nv_bfloat162 p;
    p.x = h0; p.y = h1; ((__nv_bfloat162*)hi)[0] = p;
    p.x = h2; p.y = h3; ((__nv_bfloat162*)hi)[1] = p;
    p.x = l0; p.y = l1; ((__nv_bfloat162*)lo)[0] = p;
    p.x = l2; p.y = l3; ((__nv_bfloat162*)lo)[1] = p;
}

template <bool GATHER>
__global__ void __launch_bounds__(256, 2) mg_gemm(
    const float* __restrict__ A, const float* __restrict__ Bt,
    const float* __restrict__ bias, float* __restrict__ C,
    int M, int Nc, int K, int kpad,
    const int* __restrict__ id0, const int* __restrict__ id1, int baseW) {
    extern __shared__ char sm[];
    __nv_bfloat16* sAh = (__nv_bfloat16*)(sm);
    __nv_bfloat16* sAl = (__nv_bfloat16*)(sm + TILE_B);
    __nv_bfloat16* sBh = (__nv_bfloat16*)(sm + 2 * TILE_B);
    __nv_bfloat16* sBl = (__nv_bfloat16*)(sm + 3 * TILE_B);
    float* ep = (float*)sm;

    const int tid = threadIdx.x;
    const int wid = tid >> 5;
    const int wm = wid >> 2;       // 0..1
    const int wn = wid & 3;        // 0..3
    const int m0 = blockIdx.y * 128;
    const int n0 = blockIdx.x * 128;
    const int chunks = kpad >> 5;

    wmma::fragment<wmma::accumulator, 16, 16, 16, float> acc[4][2];
#pragma unroll
    for (int i = 0; i < 4; i++)
#pragma unroll
        for (int j = 0; j < 2; j++) wmma::fill_fragment(acc[i][j], 0.f);

    const int r = tid >> 3;        // loader row (32 rows/iter, 4 iters = 128)
    const int c4 = tid & 7;        // float4 column within 32-wide K chunk

    for (int kt = 0; kt < chunks; kt++) {
        const int k0 = kt << 5;
        __syncthreads();
        // ---- load & split A, B tiles ----
#pragma unroll
        for (int it = 0; it < 4; it++) {
            int rr = r + it * 32;
            int k = k0 + c4 * 4;
            // A tile
            float4 av = make_float4(0.f, 0.f, 0.f, 0.f);
            int row = m0 + rr;
            if (GATHER) {
                if (row < M) {
                    int nid = (k0 < baseW) ? id0[row] : id1[row];
                    int kc = k - ((k0 < baseW) ? 0 : baseW);
                    av = *(const float4*)(A + (size_t)nid * baseW + kc);
                }
            } else {
                if (row < M && k < K)
                    av = *(const float4*)(A + (size_t)row * K + k);
            }
            int so = rr * TROW + c4 * 4;
            split_store(av, sAh + so, sAl + so);
            // B tile (rows always valid: Bt padded to tile multiple)
            float4 bv = *(const float4*)(Bt + (size_t)(n0 + rr) * kpad + k);
            split_store(bv, sBh + so, sBl + so);
        }
        __syncthreads();
        // ---- compute ----
#pragma unroll
        for (int ks = 0; ks < 32; ks += 16) {
            wmma::fragment<wmma::matrix_a, 16, 16, 16, __nv_bfloat16, wmma::row_major> fah[4], fal[4];
#pragma unroll
            for (int i = 0; i < 4; i++) {
                const __nv_bfloat16* pa = sAh + (wm * 64 + i * 16) * TROW + ks;
                wmma::load_matrix_sync(fah[i], pa, TROW);
                const __nv_bfloat16* pl = sAl + (wm * 64 + i * 16) * TROW + ks;
                wmma::load_matrix_sync(fal[i], pl, TROW);
            }
#pragma unroll
            for (int j = 0; j < 2; j++) {
                wmma::fragment<wmma::matrix_b, 16, 16, 16, __nv_bfloat16, wmma::col_major> fbh, fbl;
                const __nv_bfloat16* pb = sBh + (wn * 32 + j * 16) * TROW + ks;
                wmma::load_matrix_sync(fbh, pb, TROW);
                const __nv_bfloat16* pq = sBl + (wn * 32 + j * 16) * TROW + ks;
                wmma::load_matrix_sync(fbl, pq, TROW);
#pragma unroll
                for (int i = 0; i < 4; i++) {
                    wmma::mma_sync(acc[i][j], fah[i], fbh, acc[i][j]);
                    wmma::mma_sync(acc[i][j], fal[i], fbh, acc[i][j]);
                    wmma::mma_sync(acc[i][j], fah[i], fbl, acc[i][j]);
                }
            }
        }
    }

    // ---- epilogue: stage in SMEM, guarded global write ----
    __syncthreads();
#pragma unroll
    for (int i = 0; i < 4; i++)
#pragma unroll
        for (int j = 0; j < 2; j++)
            wmma::store_matrix_sync(ep + (wm * 64 + i * 16) * 128 + wn * 32 + j * 16,
                                    acc[i][j], 128, wmma::mem_row_major);
    __syncthreads();
    if ((Nc & 3) == 0) {
#pragma unroll
        for (int t = 0; t < 16; t++) {
            int idx = tid + 256 * t;
            int rr = idx >> 5, cc = idx & 31;
            int row = m0 + rr, col = n0 + cc * 4;
            if (row < M && col < Nc) {
                float4 v = *(float4*)(ep + rr * 128 + cc * 4);
                if (bias) {
                    v.x += bias[col]; v.y += bias[col + 1];
                    v.z += bias[col + 2]; v.w += bias[col + 3];
                }
                *(float4*)(C + (size_t)row * Nc + col) = v;
            }
        }
    } else {
#pragma unroll
        for (int t = 0; t < 64; t++) {
            int idx = tid + 256 * t;
            int rr = idx >> 7, cc = idx & 127;
            int row = m0 + rr, col = n0 + cc;
            if (row < M && col < Nc) {
                float v = ep[rr * 128 + cc];
                if (bias) v += bias[col];
                C[(size_t)row * Nc + col] = v;
            }
        }
    }
}

// ======================= attention logits =======================
__global__ void sdot_kernel(const float* __restrict__ h, const float* __restrict__ a_src,
                            const float* __restrict__ a_dst, float* __restrict__ s,
                            float* __restrict__ d) {
    __shared__ float4 sh[256];
    int n = blockIdx.x, t = threadIdx.x;
    float h0 = h[(size_t)n * 512 + t];
    float h1 = h[(size_t)n * 512 + 256 + t];
    float4 v = make_float4(h0 * a_src[t], h0 * a_dst[t],
                           h1 * a_src[256 + t], h1 * a_dst[256 + t]);
    sh[t] = v;
    __syncthreads();
    for (int o = 128; o > 0; o >>= 1) {
        if (t < o) {
            float4 w = sh[t + o];
            float4 m = sh[t];
            m.x += w.x; m.y += w.y; m.z += w.z; m.w += w.w;
            sh[t] = m;
        }
        __syncthreads();
    }
    if (t == 0) {
        float4 r = sh[0];
        s[2 * n] = r.x; d[2 * n] = r.y; s[2 * n + 1] = r.z; d[2 * n + 1] = r.w;
    }
}

__device__ __forceinline__ float4 f4fma(float4 a, float w, float4 acc) {
    acc.x = fmaf(a.x, w, acc.x); acc.y = fmaf(a.y, w, acc.y);
    acc.z = fmaf(a.z, w, acc.z); acc.w = fmaf(a.w, w, acc.w);
    return acc;
}

// ======================= GAT softmax + aggregation =======================
__global__ void gat_aggregate(const float* __restrict__ h, const float* __restrict__ s,
                              const float* __restrict__ d, const int* __restrict__ rowptr,
                              const int* __restrict__ csr, const float* __restrict__ bias,
                              float* __restrict__ out) {
    int warp = (blockIdx.x * blockDim.x + threadIdx.x) >> 5;
    int lane = threadIdx.x & 31;
    if (warp >= NND) return;
    int n = warp;
    int beg = rowptr[n], end = rowptr[n + 1];
    float d0 = d[2 * n], d1 = d[2 * n + 1];
    float self0 = lrelu(s[2 * n] + d0);
    float self1 = lrelu(s[2 * n + 1] + d1);

    float m0 = self0, m1 = self1;
    for (int i = beg + lane; i < end; i += 32) {
        int src = csr[i];
        m0 = fmaxf(m0, lrelu(s[2 * src] + d0));
        m1 = fmaxf(m1, lrelu(s[2 * src + 1] + d1));
    }
#pragma unroll
    for (int o = 16; o; o >>= 1) {
        m0 = fmaxf(m0, __shfl_xor_sync(0xffffffffu, m0, o));
        m1 = fmaxf(m1, __shfl_xor_sync(0xffffffffu, m1, o));
    }
    float z0 = (lane == 0) ? __expf(self0 - m0) : 0.f;
    float z1 = (lane == 0) ? __expf(self1 - m1) : 0.f;
    for (int i = beg + lane; i < end; i += 32) {
        int src = csr[i];
        z0 += __expf(lrelu(s[2 * src] + d0) - m0);
        z1 += __expf(lrelu(s[2 * src + 1] + d1) - m1);
    }
#pragma unroll
    for (int o = 16; o; o >>= 1) {
        z0 += __shfl_xor_sync(0xffffffffu, z0, o);
        z1 += __shfl_xor_sync(0xffffffffu, z1, o);
    }
    float inv0 = 1.f / (z0 + 1e-16f), inv1 = 1.f / (z1 + 1e-16f);

    const float4* h4 = (const float4*)h;
    float4 a0 = {0, 0, 0, 0}, a1 = a0, a2 = a0, a3 = a0;
    {
        float w0 = __expf(self0 - m0) * inv0;
        float w1 = __expf(self1 - m1) * inv1;
        const float4* row = h4 + (size_t)n * 128;
        a0 = f4fma(row[lane], w0, a0);
        a1 = f4fma(row[lane + 32], w0, a1);
        a2 = f4fma(row[lane + 64], w1, a2);
        a3 = f4fma(row[lane + 96], w1, a3);
    }
    for (int i = beg; i < end; i++) {
        int src = csr[i];
        float w0 = __expf(lrelu(s[2 * src] + d0) - m0) * inv0;
        float w1 = __expf(lrelu(s[2 * src + 1] + d1) - m1) * inv1;
        const float4* row = h4 + (size_t)src * 128;
        a0 = f4fma(row[lane], w0, a0);
        a1 = f4fma(row[lane + 32], w0, a1);
        a2 = f4fma(row[lane + 64], w1, a2);
        a3 = f4fma(row[lane + 96], w1, a3);
    }
    const float4* b4 = (const float4*)bias;
    float4 bA = b4[lane], bB = b4[lane + 32];
    float4 r0, r1;
    r0.x = (a0.x + a2.x) * 0.5f + bA.x; r0.y = (a0.y + a2.y) * 0.5f + bA.y;
    r0.z = (a0.z + a2.z) * 0.5f + bA.z; r0.w = (a0.w + a2.w) * 0.5f + bA.w;
    r1.x = (a1.x + a3.x) * 0.5f + bB.x; r1.y = (a1.y + a3.y) * 0.5f + bB.y;
    r1.z = (a1.z + a3.z) * 0.5f + bB.z; r1.w = (a1.w + a3.w) * 0.5f + bB.w;
    float4* o4 = (float4*)out;
    o4[(size_t)n * 64 + lane] = r0;
    o4[(size_t)n * 64 + lane + 32] = r1;
}

// ======================= batch norm (two pass) =======================
__global__ void bn_stats(const float* __restrict__ x, float* __restrict__ sums,
                         int rows, int C, int rowsPerBlock) {
    int c = threadIdx.x;
    int r0 = blockIdx.x * rowsPerBlock;
    int r1 = min(rows, r0 + rowsPerBlock);
    float s = 0.f, q = 0.f;
    for (int r = r0; r < r1; r++) {
        float v = x[(size_t)r * C + c];
        s += v;
        q += v * v;
    }
    atomicAdd(&sums[c], s);
    atomicAdd(&sums[C + c], q);
}

__global__ void bn_apply(float* __restrict__ x, const float* __restrict__ sums,
                         const float* __restrict__ g, const float* __restrict__ b,
                         int rows, int C) {
    size_t i = (size_t)blockIdx.x * blockDim.x + threadIdx.x;
    if (i >= (size_t)rows * C) return;
    int c = (int)(i % C);
    float mu = sums[c] / rows;
    float var = sums[C + c] / rows - mu * mu;
    float y = g[c] * (x[i] - mu) * rsqrtf(var + 1e-5f) + b[c];
    x[i] = fmaxf(y, 0.f);
}

// ======================= launch =======================
extern "C" void kernel_launch(void* const* d_in, const int* in_sizes, int n_in,
                              void* d_out, int out_size) {
    const int*   edge_index = (const int*)d_in[0];
    const float* x      = (const float*)d_in[1];
    const int*   edge_id = (const int*)d_in[2];
    const float* W1     = (const float*)d_in[3];
    const float* a_src1 = (const float*)d_in[4];
    const float* a_dst1 = (const float*)d_in[5];
    const float* b1     = (const float*)d_in[6];
    const float* bn1_g  = (const float*)d_in[7];
    const float* bn1_b  = (const float*)d_in[8];
    const float* W2     = (const float*)d_in[9];
    const float* a_src2 = (const float*)d_in[10];
    const float* a_dst2 = (const float*)d_in[11];
    const float* b2     = (const float*)d_in[12];
    const float* bn2_g  = (const float*)d_in[13];
    const float* bn2_b  = (const float*)d_in[14];
    const float* lw1    = (const float*)d_in[15];
    const float* lb1    = (const float*)d_in[16];
    const float* bn3_g  = (const float*)d_in[17];
    const float* bn3_b  = (const float*)d_in[18];
    const float* lw2    = (const float*)d_in[19];
    const float* lb2    = (const float*)d_in[20];
    const float* bn4_g  = (const float*)d_in[21];
    const float* bn4_b  = (const float*)d_in[22];
    const float* fw     = (const float*)d_in[23];
    const float* fb     = (const float*)d_in[24];
    float* out = (float*)d_out;

    float *h, *feat, *s, *d, *z1, *z2, *sums;
    float *w1t, *w2t, *lw1t, *lw2t, *fwt;
    int *deg, *rowptr, *cursor, *csr;
    cudaGetSymbolAddress((void**)&h, g_h);
    cudaGetSymbolAddress((void**)&feat, g_feat);
    cudaGetSymbolAddress((void**)&s, g_s);
    cudaGetSymbolAddress((void**)&d, g_d);
    cudaGetSymbolAddress((void**)&z1, g_z1);
    cudaGetSymbolAddress((void**)&z2, g_z2);
    cudaGetSymbolAddress((void**)&sums, g_sums);
    cudaGetSymbolAddress((void**)&deg, g_deg);
    cudaGetSymbolAddress((void**)&rowptr, g_rowptr);
    cudaGetSymbolAddress((void**)&cursor, g_cursor);
    cudaGetSymbolAddress((void**)&csr, g_csr);
    cudaGetSymbolAddress((void**)&w1t, g_w1t);
    cudaGetSymbolAddress((void**)&w2t, g_w2t);
    cudaGetSymbolAddress((void**)&lw1t, g_lw1t);
    cudaGetSymbolAddress((void**)&lw2t, g_lw2t);
    cudaGetSymbolAddress((void**)&fwt, g_fwt);

    cudaFuncSetAttribute(mg_gemm<false>, cudaFuncAttributeMaxDynamicSharedMemorySize,
                         MG_SMEM);
    cudaFuncSetAttribute(mg_gemm<true>, cudaFuncAttributeMaxDynamicSharedMemorySize,
                         MG_SMEM);

    // ---- weight transposes (Bt = W^T, zero padded) ----
    transposeW<<<(512 * 576 + 255) / 256, 256>>>(W1, w1t, FIN, 512, 512, 576);
    transposeW<<<(512 * 256 + 255) / 256, 256>>>(W2, w2t, C1, 512, 512, 256);
    transposeW<<<(128 * 512 + 255) / 256, 256>>>(lw1, lw1t, 512, C2, 128, 512);
    transposeW<<<(128 * 128 + 255) / 256, 256>>>(lw2, lw2t, C2, C2, 128, 128);
    transposeW<<<(128 * 128 + 255) / 256, 256>>>(fw, fwt, C2, NC, 128, 128);

    // ---- CSR build ----
    zero_i<<<(NND + 255) / 256, 256>>>(deg, NND);
    count_deg<<<(NE + 255) / 256, 256>>>(edge_index, deg);
    scan_kernel<<<1, 1024>>>(deg, rowptr, cursor);
    fill_csr<<<(NE + 255) / 256, 256>>>(edge_index, cursor, csr);

    const int mt_n = (NND + 127) / 128;   // 391
    const int mt_p = NP / 128;            // 2048

    // ---- GAT layer 1 ----
    mg_gemm<false><<<dim3(4, mt_n), 256, MG_SMEM>>>(
        x, w1t, nullptr, h, NND, 512, FIN, 576, nullptr, nullptr, 0);
    sdot_kernel<<<NND, 256>>>(h, a_src1, a_dst1, s, d);
    gat_aggregate<<<(NND * 32 + 255) / 256, 256>>>(h, s, d, rowptr, csr, b1, feat);
    zero_f<<<2, 256>>>(sums, 512);
    bn_stats<<<(NND + 511) / 512, 256>>>(feat, sums, NND, C1, 512);
    bn_apply<<<(int)(((size_t)NND * C1 + 255) / 256), 256>>>(feat, sums, bn1_g, bn1_b, NND, C1);

    // ---- GAT layer 2 ----
    mg_gemm<false><<<dim3(4, mt_n), 256, MG_SMEM>>>(
        feat, w2t, nullptr, h, NND, 512, C1, 256, nullptr, nullptr, 0);
    sdot_kernel<<<NND, 256>>>(h, a_src2, a_dst2, s, d);
    gat_aggregate<<<(NND * 32 + 255) / 256, 256>>>(h, s, d, rowptr, csr, b2, feat);
    zero_f<<<2, 256>>>(sums, 512);
    bn_stats<<<(NND + 511) / 512, 256>>>(feat, sums, NND, C1, 512);
    bn_apply<<<(int)(((size_t)NND * C1 + 255) / 256), 256>>>(feat, sums, bn2_g, bn2_b, NND, C1);

    // ---- pair MLP ----
    mg_gemm<true><<<dim3(1, mt_p), 256, MG_SMEM>>>(
        feat, lw1t, lb1, z1, NP, C2, 512, 512, edge_id, edge_id + NP, C1);
    zero_f<<<1, 256>>>(sums, 256);
    bn_stats<<<(NP + 1023) / 1024, C2>>>(z1, sums, NP, C2, 1024);
    bn_apply<<<(int)(((size_t)NP * C2 + 255) / 256), 256>>>(z1, sums, bn3_g, bn3_b, NP, C2);

    mg_gemm<false><<<dim3(1, mt_p), 256, MG_SMEM>>>(
        z1, lw2t, lb2, z2, NP, C2, C2, 128, nullptr, nullptr, 0);
    zero_f<<<1, 256>>>(sums, 256);
    bn_stats<<<(NP + 1023) / 1024, C2>>>(z2, sums, NP, C2, 1024);
    bn_apply<<<(int)(((size_t)NP * C2 + 255) / 256), 256>>>(z2, sums, bn4_g, bn4_b, NP, C2);

    mg_gemm<false><<<dim3(1, mt_p), 256, MG_SMEM>>>(
        z2, fwt, fb, out, NP, NC, C2, 128, nullptr, nullptr, 0);
}